// round 8
// baseline (speedup 1.0000x reference)
#include <cuda_runtime.h>

#define DEGREE   6
#define WIDTH    7          // DEGREE - START_DEGREE + 1
#define FEAT     1024       // in_features
#define OUTF     1024       // out_features
#define THREADS  512
#define NWARPS   16
#define ROWS_PER_BLOCK 8    // 2 warps per row, 16 features per lane

__device__ __forceinline__ float ex2f(float x) {
    float r; asm("ex2.approx.f32 %0, %1;" : "=f"(r) : "f"(x)); return r;
}
__device__ __forceinline__ float clipf(float v) {
    return fminf(fmaxf(v, -100.0f), 100.0f);
}

// Scalar, low-register, high-occupancy fused kernel.
//  - 16 warps, 2 per row: each warp reduces 512 features (16/lane,
//    4x front-batched LDG.128), warp-shuffle reduce -> s_part[16][7]
//  - ONE barrier; phase 2: thread t emits cols {2t,2t+1} for all 8 rows
//    from 14 register coeffs, merging the two half-row partials on the fly
__global__ __launch_bounds__(THREADS, 3)   // force regs <= 42 -> 48 warps/SM
void hermite_fused_kernel(const float* __restrict__ x,
                          const float* __restrict__ coeffs,
                          const float* __restrict__ sigma,
                          float* __restrict__ out)
{
    __shared__ float s_part[NWARPS][WIDTH];

    const int tid  = threadIdx.x;
    const int lane = tid & 31;
    const int warp = tid >> 5;          // 0..15

    const float s     = fminf(fmaxf(sigma[0], 0.1f), 5.0f);
    const float inv_s = 1.0f / s;
    const float kexp  = -1.4426950408889634f * inv_s * inv_s; // -log2e/s^2

    // ---- Phase 1: half a row per warp (16 features/lane, front-batched) ----
    const int row  = blockIdx.x * ROWS_PER_BLOCK + (warp >> 1);
    const int half = warp & 1;
    const float4* xr = reinterpret_cast<const float4*>(x + (size_t)row * FEAT)
                       + half * (FEAT / 8);   // 128 float4 per half

    float4 xv[4];
#pragma unroll
    for (int i = 0; i < 4; ++i) xv[i] = xr[lane + 32 * i];

    float a[WIDTH];
#pragma unroll
    for (int w = 0; w < WIDTH; ++w) a[w] = 0.0f;

#pragma unroll
    for (int i = 0; i < 4; ++i) {
        const float xe[4] = { xv[i].x, xv[i].y, xv[i].z, xv[i].w };
#pragma unroll
        for (int e = 0; e < 4; ++e) {
            const float xq = xe[e];
            const float xs = xq * inv_s;
            // g = exp(-xs^2); min(xs^2,50) never binds (delta ~e-50 << tol)
            const float g  = ex2f(xq * xq * kexp);
            const float txs = xs + xs;          // 2*xs = H1

            a[0] += g;                          // g * H0
            a[1] += g * txs;                    // g * H1

            float hm2 = 1.0f;
            float hm1 = txs;

            // n = 2: clip (|H2|>100 needs |xs|>5.05 where g<8e-12) -> skip
            {
                float h = txs * hm1 - 2.0f;     // 2xs*H1 - 2*H0
                a[2] += g * h;
                hm2 = hm1;
                hm1 = h;
            }
#pragma unroll
            for (int n = 3; n <= DEGREE; ++n) {
                float h = txs * hm1 + (-2.0f * (float)(n - 1)) * hm2;
                h = clipf(h);                   // clip BEFORE recursion use
                a[n] += g * h;
                hm2 = hm1;
                hm1 = h;
            }
        }
    }

    // ---- warp-local reduction of the 7 accumulators ----
#pragma unroll
    for (int w = 0; w < WIDTH; ++w) {
#pragma unroll
        for (int off = 16; off > 0; off >>= 1)
            a[w] += __shfl_xor_sync(0xffffffffu, a[w], off);
    }
    if (lane == 0) {
#pragma unroll
        for (int w = 0; w < WIDTH; ++w)
            s_part[warp][w] = a[w];
    }

    // ---- coeff loads (lifetime starts here; latency hides behind barrier) --
    // thread t owns output columns {2t, 2t+1}: 14 contiguous floats
    float cf[14];
    {
        const float2* c2 =
            reinterpret_cast<const float2*>(coeffs + (size_t)(tid * 2) * WIDTH);
#pragma unroll
        for (int i = 0; i < 7; ++i) {
            float2 v = c2[i];
            cf[2 * i]     = v.x;
            cf[2 * i + 1] = v.y;
        }
    }

    __syncthreads();   // the ONLY barrier

    // ---- Phase 2: 8 rows x 2 output columns per thread ----
#pragma unroll
    for (int r = 0; r < ROWS_PER_BLOCK; ++r) {
        float bs[WIDTH];
#pragma unroll
        for (int w = 0; w < WIDTH; ++w)
            bs[w] = s_part[2 * r][w] + s_part[2 * r + 1][w];  // merge halves

        float v0 = 0.0f, v1 = 0.0f;
#pragma unroll
        for (int w = 0; w < WIDTH; ++w) {
            v0 += bs[w] * cf[w];
            v1 += bs[w] * cf[WIDTH + w];
        }
        const int orow = blockIdx.x * ROWS_PER_BLOCK + r;
        float2 o = { v0, v1 };
        reinterpret_cast<float2*>(out + (size_t)orow * OUTF)[tid] = o;
    }
}

extern "C" void kernel_launch(void* const* d_in, const int* in_sizes, int n_in,
                              void* d_out, int out_size)
{
    const float* x      = (const float*)d_in[0];   // (4096, 1024)
    const float* coeffs = (const float*)d_in[1];   // (1024, 7)
    const float* sigma  = (const float*)d_in[2];   // (1,)
    float* out          = (float*)d_out;           // (4096, 1024)

    const int batch  = in_sizes[0] / FEAT;         // 4096
    const int nblock = batch / ROWS_PER_BLOCK;     // 512

    hermite_fused_kernel<<<nblock, THREADS>>>(x, coeffs, sigma, out);
}

// round 9
// speedup vs baseline: 1.1454x; 1.1454x over previous
#include <cuda_runtime.h>

#define DEGREE   6
#define WIDTH    7          // DEGREE - START_DEGREE + 1
#define FEAT     1024       // in_features
#define OUTF     1024       // out_features
#define THREADS  256
#define NWARPS   8
#define ROWS_PER_BLOCK 4    // 2 warps per row, 16 features per lane
#define GRID     592        // 148 SMs x 4 resident blocks
#define NGROUPS  (4096 / ROWS_PER_BLOCK)   // 1024

__device__ __forceinline__ float ex2f(float x) {
    float r; asm("ex2.approx.f32 %0, %1;" : "=f"(r) : "f"(x)); return r;
}
__device__ __forceinline__ float clipf(float v) {
    return fminf(fmaxf(v, -100.0f), 100.0f);
}

// ---------- phase-1 eval: 16 features -> 7 partial sums ----------
__device__ __forceinline__ void eval16(const float4* __restrict__ xv,
                                       float inv_s, float kexp,
                                       float* __restrict__ a)
{
#pragma unroll
    for (int w = 0; w < WIDTH; ++w) a[w] = 0.0f;

#pragma unroll
    for (int i = 0; i < 4; ++i) {
        const float xe[4] = { xv[i].x, xv[i].y, xv[i].z, xv[i].w };
#pragma unroll
        for (int e = 0; e < 4; ++e) {
            const float xq  = xe[e];
            const float txs = xq * (2.0f * inv_s);   // 2*xs = H1
            // g = exp(-xs^2); min(xs^2,50) never binds (delta ~e-50 << tol)
            const float g   = ex2f(xq * xq * kexp);

            a[0] += g;                               // g * H0
            a[1] += g * txs;                         // g * H1

            float hm2 = txs;                         // after n=2 step: hm2=H1
            float h   = txs * txs - 2.0f;            // H2 (clip can't bind
            a[2] += g * h;                           //  where g > 8e-12)
            float hm1 = h;
#pragma unroll
            for (int n = 3; n <= DEGREE; ++n) {
                float t = (-2.0f * (float)(n - 1)) * hm2;  // FMUL-imm
                h = fmaf(txs, hm1, t);
                h = clipf(h);                        // clip BEFORE recursion use
                a[n] += g * h;
                hm2 = hm1;
                hm1 = h;
            }
        }
    }
}

__device__ __forceinline__ void reduce_store(float* __restrict__ a,
                                             float (*s_part)[WIDTH],
                                             int warp, int lane)
{
#pragma unroll
    for (int w = 0; w < WIDTH; ++w) {
#pragma unroll
        for (int off = 16; off > 0; off >>= 1)
            a[w] += __shfl_xor_sync(0xffffffffu, a[w], off);
    }
    if (lane == 0) {
#pragma unroll
        for (int w = 0; w < WIDTH; ++w)
            s_part[warp][w] = a[w];
    }
}

__device__ __forceinline__ void phase2(const float (*s_part)[WIDTH],
                                       const float* __restrict__ cf,
                                       float* __restrict__ out,
                                       int group, int tid)
{
#pragma unroll
    for (int r = 0; r < ROWS_PER_BLOCK; ++r) {
        float bs[WIDTH];
#pragma unroll
        for (int w = 0; w < WIDTH; ++w)
            bs[w] = s_part[2 * r][w] + s_part[2 * r + 1][w];

        float4 o;
        float* op = reinterpret_cast<float*>(&o);
#pragma unroll
        for (int i = 0; i < 4; ++i) {
            float v = 0.0f;
#pragma unroll
            for (int w = 0; w < WIDTH; ++w)
                v += bs[w] * cf[i * WIDTH + w];
            op[i] = v;
        }
        const int orow = group * ROWS_PER_BLOCK + r;
        reinterpret_cast<float4*>(out + (size_t)orow * OUTF)[tid] = o;
    }
}

// Persistent 2-group pipelined kernel. Block b handles groups b and b+592.
// Group-2 x loads + coeff loads are issued right after eval(g0), so their
// ~580-cycle latency hides behind reduce + barrier + phase2(g0).
__global__ __launch_bounds__(THREADS, 4)   // keep 4 blocks/SM (regs <= 64)
void hermite_fused_kernel(const float* __restrict__ x,
                          const float* __restrict__ coeffs,
                          const float* __restrict__ sigma,
                          float* __restrict__ out)
{
    __shared__ float s_partA[NWARPS][WIDTH];
    __shared__ float s_partB[NWARPS][WIDTH];

    const int tid  = threadIdx.x;
    const int lane = tid & 31;
    const int warp = tid >> 5;

    const float s     = fminf(fmaxf(sigma[0], 0.1f), 5.0f);
    const float inv_s = 1.0f / s;
    const float kexp  = -1.4426950408889634f * inv_s * inv_s;

    const int g0 = blockIdx.x;
    const int g1 = blockIdx.x + GRID;
    const bool has2 = (g1 < NGROUPS);

    const int half = warp & 1;
    const int roff = (warp >> 1);   // row within group

    // ---- group 0: load + eval ----
    {
        const int row0 = g0 * ROWS_PER_BLOCK + roff;
        const float4* xr =
            reinterpret_cast<const float4*>(x + (size_t)row0 * FEAT)
            + half * (FEAT / 8);
        float4 xv[4];
#pragma unroll
        for (int i = 0; i < 4; ++i) xv[i] = xr[lane + 32 * i];

        float a[WIDTH];
        eval16(xv, inv_s, kexp, a);

        // ---- prefetch group 1's x and the coeffs (latency hidden below) ----
        float4 xv2[4];
        if (has2) {
            const int row1 = g1 * ROWS_PER_BLOCK + roff;
            const float4* xr2 =
                reinterpret_cast<const float4*>(x + (size_t)row1 * FEAT)
                + half * (FEAT / 8);
#pragma unroll
            for (int i = 0; i < 4; ++i) xv2[i] = xr2[lane + 32 * i];
        }
        float4 c[7];
        {
            const float4* c4 = reinterpret_cast<const float4*>(
                coeffs + (size_t)(tid * 4) * WIDTH);
#pragma unroll
            for (int i = 0; i < 7; ++i) c[i] = c4[i];
        }
        const float* cf = reinterpret_cast<const float*>(c);

        reduce_store(a, s_partA, warp, lane);
        __syncthreads();                       // barrier 1
        phase2(s_partA, cf, out, g0, tid);

        // ---- group 1: eval + reduce (into buffer B) + phase 2 ----
        if (has2) {
            float a2[WIDTH];
            eval16(xv2, inv_s, kexp, a2);
            reduce_store(a2, s_partB, warp, lane);
            __syncthreads();                   // barrier 2
            phase2(s_partB, cf, out, g1, tid);
        }
    }
}

extern "C" void kernel_launch(void* const* d_in, const int* in_sizes, int n_in,
                              void* d_out, int out_size)
{
    const float* x      = (const float*)d_in[0];   // (4096, 1024)
    const float* coeffs = (const float*)d_in[1];   // (1024, 7)
    const float* sigma  = (const float*)d_in[2];   // (1,)
    float* out          = (float*)d_out;           // (4096, 1024)

    hermite_fused_kernel<<<GRID, THREADS>>>(x, coeffs, sigma, out);
}